// round 2
// baseline (speedup 1.0000x reference)
#include <cuda_runtime.h>

#define B_    8
#define N_    1024
#define NIN_  64
#define H_    128
#define CTXF_ 192
#define TI_   4
#define BM_   64
#define BN_   64
#define KC_   32

// Scratch (no allocation allowed in kernel_launch)
__device__ float g_hr[B_*N_*H_];          // [B,N,H]   relu'd right hidden
__device__ float g_t [B_*N_*2*H_];        // [B,N,2,H] t = hl @ W_bil
__device__ float g_Wlt[CTXF_*H_];         // W_l transposed -> [f][h]
__device__ float g_Wrt[CTXF_*H_];         // W_r transposed -> [f][h]

// ---------------------------------------------------------------------------
// Tiny one-time transpose so the MLP kernel reads W coalesced ([f][h], h fast)
// ---------------------------------------------------------------------------
__global__ void transpose_w_kernel(const float* __restrict__ Wl,
                                   const float* __restrict__ Wr)
{
    int idx = blockIdx.x * 256 + threadIdx.x;          // over 192*128 = 24576
    if (idx < CTXF_*H_) {
        int f = idx >> 7;         // /128
        int h = idx & 127;
        g_Wlt[idx] = Wl[h*CTXF_ + f];
        g_Wrt[idx] = Wr[h*CTXF_ + f];
    }
}

// ---------------------------------------------------------------------------
// Prep: context expansion + MLP (hl, hr) + t = einsum('h,khg->kg', hl, Wbil)
// One block handles TI_=4 consecutive sequence positions of one batch.
// 128 threads: thread == h index for the MLP part, thread == g for the t part.
// ---------------------------------------------------------------------------
__global__ void __launch_bounds__(128) prep_kernel(
    const float* __restrict__ x,
    const float* __restrict__ bl,
    const float* __restrict__ br,
    const float* __restrict__ Wbil)
{
    __shared__ __align__(16) float sx[(TI_+2)*NIN_];   // rows i0-1 .. i0+4
    __shared__ __align__(16) float s_hl[TI_][H_];

    const int blk = blockIdx.x;
    const int b   = blk >> 8;               // N/TI = 256 blocks per batch
    const int i0  = (blk & 255) * TI_;
    const int tid = threadIdx.x;

    // Load 6 rows of x (zero-padded at sequence edges)
    #pragma unroll
    for (int l = 0; l < 3; l++) {
        int idx = tid + l*128;              // 0..383
        int r   = idx >> 6;                 // 0..5
        int row = i0 - 1 + r;
        float v = 0.0f;
        if (row >= 0 && row < N_) v = x[(b*N_ + row)*NIN_ + (idx & 63)];
        sx[idx] = v;
    }
    __syncthreads();

    const int h = tid;
    float accl[TI_], accr[TI_];
    {
        float blv = bl[h], brv = br[h];
        #pragma unroll
        for (int r = 0; r < TI_; r++) { accl[r] = blv; accr[r] = brv; }
    }

    const float4* sx4 = reinterpret_cast<const float4*>(sx);

    // Feature segments:
    //   seg0: x[i]   (both sides)
    //   seg1: left = x[i-1], right = x[i+1]
    //   seg2: left = x[i+1], right = x[i-1]
    #pragma unroll
    for (int seg = 0; seg < 3; seg++) {
        const int dl = (seg == 0) ? 0 : (seg == 1 ? -1 : 1);
        const int dr = -dl;
        #pragma unroll 4
        for (int f4 = 0; f4 < 16; f4++) {
            const int fbase = seg*64 + f4*4;
            float wl0 = g_Wlt[(fbase+0)*H_ + h];
            float wl1 = g_Wlt[(fbase+1)*H_ + h];
            float wl2 = g_Wlt[(fbase+2)*H_ + h];
            float wl3 = g_Wlt[(fbase+3)*H_ + h];
            float wr0 = g_Wrt[(fbase+0)*H_ + h];
            float wr1 = g_Wrt[(fbase+1)*H_ + h];
            float wr2 = g_Wrt[(fbase+2)*H_ + h];
            float wr3 = g_Wrt[(fbase+3)*H_ + h];
            #pragma unroll
            for (int r = 0; r < TI_; r++) {
                float4 xl = sx4[(r+1+dl)*16 + f4];
                float4 xr = sx4[(r+1+dr)*16 + f4];
                accl[r] = fmaf(wl0, xl.x, accl[r]);
                accl[r] = fmaf(wl1, xl.y, accl[r]);
                accl[r] = fmaf(wl2, xl.z, accl[r]);
                accl[r] = fmaf(wl3, xl.w, accl[r]);
                accr[r] = fmaf(wr0, xr.x, accr[r]);
                accr[r] = fmaf(wr1, xr.y, accr[r]);
                accr[r] = fmaf(wr2, xr.z, accr[r]);
                accr[r] = fmaf(wr3, xr.w, accr[r]);
            }
        }
    }

    #pragma unroll
    for (int r = 0; r < TI_; r++) {
        s_hl[r][h] = fmaxf(accl[r], 0.0f);
        g_hr[(b*N_ + i0 + r)*H_ + h] = fmaxf(accr[r], 0.0f);
    }
    __syncthreads();

    // t[k][r] = sum_h s_hl[r][h] * Wbil[k][h][g],  thread owns one g
    const int g = tid;
    float t0[TI_] = {0.f,0.f,0.f,0.f};
    float t1[TI_] = {0.f,0.f,0.f,0.f};
    #pragma unroll 8
    for (int h0 = 0; h0 < H_; h0 += 4) {
        float hv[TI_][4];
        #pragma unroll
        for (int r = 0; r < TI_; r++)
            *reinterpret_cast<float4*>(hv[r]) =
                *reinterpret_cast<const float4*>(&s_hl[r][h0]);
        #pragma unroll
        for (int hh = 0; hh < 4; hh++) {
            float w0 = Wbil[(h0+hh)*H_ + g];            // k=0
            float w1 = Wbil[H_*H_ + (h0+hh)*H_ + g];    // k=1
            #pragma unroll
            for (int r = 0; r < TI_; r++) {
                t0[r] = fmaf(hv[r][hh], w0, t0[r]);
                t1[r] = fmaf(hv[r][hh], w1, t1[r]);
            }
        }
    }
    #pragma unroll
    for (int r = 0; r < TI_; r++) {
        int rowbase = (b*N_ + i0 + r)*2*H_;
        g_t[rowbase +      g] = t0[r];
        g_t[rowbase + H_ + g] = t1[r];
    }
}

// ---------------------------------------------------------------------------
// Pairwise: out[b,i,j,k] = sum_g t[b,i,k,g] * hr[b,j,g] + b_bil[k]
// 64x64 tile, 256 threads, 4i x 4j x 2k register tile, KC=32 K-chunks.
// sA kept natural ([c=i*2+k][g], g fast); sB XOR-swizzled over float4 slots so
// the j-strided float4 reads are conflict-free per quarter-warp.
// ---------------------------------------------------------------------------
__global__ void __launch_bounds__(256) pair_kernel(
    const float* __restrict__ bbil, float* __restrict__ out)
{
    __shared__ __align__(16) float sA[2*BM_*KC_];   // [c][g]  c = i_local*2 + k
    __shared__ __align__(16) float sB[BN_*KC_];     // [j][q^swz]

    const int b   = blockIdx.z;
    const int ib  = blockIdx.y * BM_;
    const int jb  = blockIdx.x * BN_;
    const int tid = threadIdx.x;
    const int tx  = tid & 15;     // j group
    const int ty  = tid >> 4;     // i group

    const float* tb = g_t  + (b*N_ + ib)*2*H_;   // tile rows are contiguous
    const float* hb = g_hr + (b*N_ + jb)*H_;

    float acc[2][4][4];
    #pragma unroll
    for (int k = 0; k < 2; k++)
        #pragma unroll
        for (int ii = 0; ii < 4; ii++)
            #pragma unroll
            for (int jj = 0; jj < 4; jj++) acc[k][ii][jj] = 0.0f;

    for (int g0 = 0; g0 < H_; g0 += KC_) {
        // A tile: 128 rows x 8 float4  (coalesced; natural layout, stores are
        // conflict-free: within a quarter-warp q is distinct)
        #pragma unroll
        for (int l = 0; l < 4; l++) {
            int idx = tid + l*256;         // 0..1023
            int c   = idx >> 3;            // 0..127
            int q   = idx & 7;
            float4 v = *reinterpret_cast<const float4*>(tb + c*H_ + g0 + q*4);
            *reinterpret_cast<float4*>(sA + c*KC_ + q*4) = v;
        }
        // B tile: 64 rows x 8 float4, swizzled: slot q stored at q ^ ((j>>2)&7)
        #pragma unroll
        for (int l = 0; l < 2; l++) {
            int idx = tid + l*256;         // 0..511
            int j   = idx >> 3;            // 0..63
            int q   = idx & 7;
            float4 v = *reinterpret_cast<const float4*>(hb + j*H_ + g0 + q*4);
            int qs = q ^ ((j >> 2) & 7);
            *reinterpret_cast<float4*>(sB + j*KC_ + qs*4) = v;
        }
        __syncthreads();

        #pragma unroll
        for (int gs = 0; gs < KC_/4; gs++) {
            float4 b4[4];
            #pragma unroll
            for (int jj = 0; jj < 4; jj++) {
                int j  = tx*4 + jj;
                int qs = gs ^ (tx & 7);    // (j>>2)&7 == tx&7
                b4[jj] = *reinterpret_cast<const float4*>(sB + j*KC_ + qs*4);
            }
            float4 a4[2][4];
            #pragma unroll
            for (int ii = 0; ii < 4; ii++) {
                int cbase = (ty*4 + ii)*2;
                a4[0][ii] = *reinterpret_cast<const float4*>(sA + (cbase+0)*KC_ + gs*4);
                a4[1][ii] = *reinterpret_cast<const float4*>(sA + (cbase+1)*KC_ + gs*4);
            }
            #pragma unroll
            for (int k = 0; k < 2; k++)
                #pragma unroll
                for (int ii = 0; ii < 4; ii++)
                    #pragma unroll
                    for (int jj = 0; jj < 4; jj++) {
                        acc[k][ii][jj] = fmaf(a4[k][ii].x, b4[jj].x, acc[k][ii][jj]);
                        acc[k][ii][jj] = fmaf(a4[k][ii].y, b4[jj].y, acc[k][ii][jj]);
                        acc[k][ii][jj] = fmaf(a4[k][ii].z, b4[jj].z, acc[k][ii][jj]);
                        acc[k][ii][jj] = fmaf(a4[k][ii].w, b4[jj].w, acc[k][ii][jj]);
                    }
        }
        __syncthreads();
    }

    const float bb0 = bbil[0];
    const float bb1 = bbil[1];
    #pragma unroll
    for (int ii = 0; ii < 4; ii++) {
        int i = ib + ty*4 + ii;
        int j = jb + tx*4;
        float* o = out + ((size_t)(b*N_ + i)*N_ + j)*2;
        float4 v0, v1;
        v0.x = acc[0][ii][0] + bb0;  v0.y = acc[1][ii][0] + bb1;
        v0.z = acc[0][ii][1] + bb0;  v0.w = acc[1][ii][1] + bb1;
        v1.x = acc[0][ii][2] + bb0;  v1.y = acc[1][ii][2] + bb1;
        v1.z = acc[0][ii][3] + bb0;  v1.w = acc[1][ii][3] + bb1;
        *reinterpret_cast<float4*>(o)     = v0;
        *reinterpret_cast<float4*>(o + 4) = v1;
    }
}

// ---------------------------------------------------------------------------
extern "C" void kernel_launch(void* const* d_in, const int* in_sizes, int n_in,
                              void* d_out, int out_size)
{
    const float* x    = (const float*)d_in[0];
    const float* Wl   = (const float*)d_in[1];
    const float* bl   = (const float*)d_in[2];
    const float* Wr   = (const float*)d_in[3];
    const float* br   = (const float*)d_in[4];
    const float* Wbil = (const float*)d_in[5];
    const float* bbil = (const float*)d_in[6];
    float* out = (float*)d_out;
    (void)in_sizes; (void)n_in; (void)out_size;

    transpose_w_kernel<<<(CTXF_*H_ + 255)/256, 256>>>(Wl, Wr);
    prep_kernel<<<B_*N_/TI_, 128>>>(x, bl, br, Wbil);
    pair_kernel<<<dim3(N_/BN_, N_/BM_, B_), 256>>>(bbil, out);
}

// round 9
// speedup vs baseline: 1.0836x; 1.0836x over previous
#include <cuda_runtime.h>
#include <cuda_bf16.h>
#include <cstdint>

#define B_    8
#define N_    1024
#define NIN_  64
#define H_    128
#define CTXF_ 192
#define TI_   8

// pair-kernel tiling: 128 j  x  128 c(=i*2+k)  x  K=128 g per CTA
#define PJ_   128
#define PC_   128

// ---------------------------------------------------------------------------
// Scratch (device globals; no allocation allowed)
// hi/lo bf16 split pairs: v == hi + lo to ~16 mantissa bits
// ---------------------------------------------------------------------------
__device__ __nv_bfloat16 g_hr_hi[B_*N_*H_];     // [B,N,H]
__device__ __nv_bfloat16 g_hr_lo[B_*N_*H_];
__device__ __nv_bfloat16 g_t_hi [B_*N_*2*H_];   // [B,N,2,H]
__device__ __nv_bfloat16 g_t_lo [B_*N_*2*H_];
__device__ float g_Wlt[CTXF_*H_];               // W_l^T  [f][h]
__device__ float g_Wrt[CTXF_*H_];               // W_r^T  [f][h]

// ---------------------------------------------------------------------------
// PTX helpers (plain sm_103-legal: ldmatrix + mma.sync, NO tcgen05)
// ---------------------------------------------------------------------------
__device__ __forceinline__ uint32_t smem_u32(const void* p) {
    uint32_t a;
    asm("{ .reg .u64 t; cvta.to.shared.u64 t, %1; cvt.u32.u64 %0, t; }" : "=r"(a) : "l"(p));
    return a;
}

#define LDSM_X4(r0, r1, r2, r3, addr) \
    asm volatile("ldmatrix.sync.aligned.m8n8.x4.shared.b16 {%0,%1,%2,%3}, [%4];" \
        : "=r"(r0), "=r"(r1), "=r"(r2), "=r"(r3) : "r"(addr))

#define MMA16816(d, a, b0, b1) \
    asm volatile("mma.sync.aligned.m16n8k16.row.col.f32.bf16.bf16.f32 " \
        "{%0,%1,%2,%3},{%4,%5,%6,%7},{%8,%9},{%0,%1,%2,%3};" \
        : "+f"((d)[0]), "+f"((d)[1]), "+f"((d)[2]), "+f"((d)[3]) \
        : "r"((a)[0]), "r"((a)[1]), "r"((a)[2]), "r"((a)[3]), "r"(b0), "r"(b1))

__device__ __forceinline__ void bf16_split(float v, __nv_bfloat16& hi, __nv_bfloat16& lo) {
    hi = __float2bfloat16(v);
    lo = __float2bfloat16(v - __bfloat162float(hi));
}

// ---------------------------------------------------------------------------
// One-time weight transpose ([h][f] -> [f][h]) for coalesced MLP reads
// ---------------------------------------------------------------------------
__global__ void transpose_w_kernel(const float* __restrict__ Wl,
                                   const float* __restrict__ Wr)
{
    int idx = blockIdx.x * 256 + threadIdx.x;
    if (idx < CTXF_*H_) {
        int f = idx >> 7, h = idx & 127;
        g_Wlt[idx] = Wl[h*CTXF_ + f];
        g_Wrt[idx] = Wr[h*CTXF_ + f];
    }
}

// ---------------------------------------------------------------------------
// Prep: context expansion + MLP + t = hl @ W_bil; outputs hi/lo bf16 pairs.
// One block = TI_=8 sequence positions. 128 threads (thread = h, then = g).
// ---------------------------------------------------------------------------
__global__ void __launch_bounds__(128) prep_kernel(
    const float* __restrict__ x,
    const float* __restrict__ bl,
    const float* __restrict__ br,
    const float* __restrict__ Wbil)
{
    __shared__ __align__(16) float sx[(TI_+2)*NIN_];   // rows i0-1 .. i0+TI_
    __shared__ __align__(16) float s_hl[TI_][H_];

    const int blk = blockIdx.x;
    const int b   = blk >> 7;                // N/TI = 128 blocks per batch
    const int i0  = (blk & 127) * TI_;
    const int tid = threadIdx.x;

    #pragma unroll
    for (int l = 0; l < 5; l++) {
        int idx = tid + l*128;               // 0..639
        int r   = idx >> 6;                  // 0..9
        int row = i0 - 1 + r;
        float v = 0.0f;
        if (row >= 0 && row < N_) v = x[(b*N_ + row)*NIN_ + (idx & 63)];
        sx[idx] = v;
    }
    __syncthreads();

    const int h = tid;
    float accl[TI_], accr[TI_];
    {
        float blv = bl[h], brv = br[h];
        #pragma unroll
        for (int r = 0; r < TI_; r++) { accl[r] = blv; accr[r] = brv; }
    }

    const float4* sx4 = reinterpret_cast<const float4*>(sx);

    #pragma unroll 1
    for (int seg = 0; seg < 3; seg++) {
        const int dl = (seg == 0) ? 0 : (seg == 1 ? -1 : 1);
        const int dr = -dl;
        #pragma unroll 2
        for (int f4 = 0; f4 < 16; f4++) {
            const int fbase = seg*64 + f4*4;
            float wl0 = g_Wlt[(fbase+0)*H_ + h];
            float wl1 = g_Wlt[(fbase+1)*H_ + h];
            float wl2 = g_Wlt[(fbase+2)*H_ + h];
            float wl3 = g_Wlt[(fbase+3)*H_ + h];
            float wr0 = g_Wrt[(fbase+0)*H_ + h];
            float wr1 = g_Wrt[(fbase+1)*H_ + h];
            float wr2 = g_Wrt[(fbase+2)*H_ + h];
            float wr3 = g_Wrt[(fbase+3)*H_ + h];
            #pragma unroll
            for (int r = 0; r < TI_; r++) {
                float4 xl = sx4[(r+1+dl)*16 + f4];
                float4 xr = sx4[(r+1+dr)*16 + f4];
                accl[r] = fmaf(wl0, xl.x, accl[r]);
                accl[r] = fmaf(wl1, xl.y, accl[r]);
                accl[r] = fmaf(wl2, xl.z, accl[r]);
                accl[r] = fmaf(wl3, xl.w, accl[r]);
                accr[r] = fmaf(wr0, xr.x, accr[r]);
                accr[r] = fmaf(wr1, xr.y, accr[r]);
                accr[r] = fmaf(wr2, xr.z, accr[r]);
                accr[r] = fmaf(wr3, xr.w, accr[r]);
            }
        }
    }

    #pragma unroll
    for (int r = 0; r < TI_; r++) {
        s_hl[r][h] = fmaxf(accl[r], 0.0f);
        float hv = fmaxf(accr[r], 0.0f);
        __nv_bfloat16 hi, lo; bf16_split(hv, hi, lo);
        size_t o = (size_t)(b*N_ + i0 + r)*H_ + h;
        g_hr_hi[o] = hi;  g_hr_lo[o] = lo;
    }
    __syncthreads();

    // t[k][r][g] = sum_h s_hl[r][h] * Wbil[k][h][g]; thread owns one g
    const int g = tid;
    float t0[TI_], t1[TI_];
    #pragma unroll
    for (int r = 0; r < TI_; r++) { t0[r] = 0.f; t1[r] = 0.f; }

    #pragma unroll 2
    for (int h0 = 0; h0 < H_; h0 += 4) {
        float w0[4], w1[4];
        #pragma unroll
        for (int hh = 0; hh < 4; hh++) {
            w0[hh] = Wbil[(h0+hh)*H_ + g];
            w1[hh] = Wbil[H_*H_ + (h0+hh)*H_ + g];
        }
        #pragma unroll
        for (int r = 0; r < TI_; r++) {
            float4 hv = *reinterpret_cast<const float4*>(&s_hl[r][h0]);
            t0[r] = fmaf(hv.x, w0[0], t0[r]);  t1[r] = fmaf(hv.x, w1[0], t1[r]);
            t0[r] = fmaf(hv.y, w0[1], t0[r]);  t1[r] = fmaf(hv.y, w1[1], t1[r]);
            t0[r] = fmaf(hv.z, w0[2], t0[r]);  t1[r] = fmaf(hv.z, w1[2], t1[r]);
            t0[r] = fmaf(hv.w, w0[3], t0[r]);  t1[r] = fmaf(hv.w, w1[3], t1[r]);
        }
    }
    #pragma unroll
    for (int r = 0; r < TI_; r++) {
        size_t rowbase = (size_t)(b*N_ + i0 + r)*2*H_;
        __nv_bfloat16 hi, lo;
        bf16_split(t0[r], hi, lo);
        g_t_hi[rowbase + g] = hi;       g_t_lo[rowbase + g] = lo;
        bf16_split(t1[r], hi, lo);
        g_t_hi[rowbase + H_ + g] = hi;  g_t_lo[rowbase + H_ + g] = lo;
    }
}

// ---------------------------------------------------------------------------
// Pairwise GEMM, bf16x3 compensated HMMA:
//   D = Ahi*Bhi + Ahi*Blo + Alo*Bhi   (A = hr rows j, B = t rows c=i*2+k)
//   Single smem stage: 4 slabs of 128 rows x 256B (swizzled) = 128 KB.
//   8 warps = 2(j) x 4(c); warp tile 64x32; per k-step: 12 LDSM -> 48 MMA.
// ---------------------------------------------------------------------------
#define SLAB_   (PJ_*256)          // 32 KB
#define SM_PAIR (4*SLAB_)          // 131072

__global__ void __launch_bounds__(256, 1) pair_kernel(
    const float* __restrict__ bbil, float* __restrict__ out)
{
    extern __shared__ __align__(16) char smem[];
    const uint32_t sAhi = smem_u32(smem);
    const uint32_t sAlo = sAhi + SLAB_;
    const uint32_t sBhi = sAhi + 2*SLAB_;
    const uint32_t sBlo = sAhi + 3*SLAB_;

    const int tid = threadIdx.x;
    const int wid = tid >> 5;
    const int lid = tid & 31;
    const int b   = blockIdx.z;
    const int cb  = blockIdx.x * PC_;              // c-row base (i*2+k space)
    const int jb  = blockIdx.y * PJ_;

    // ---- cooperative tile loads (16B chunks, q ^ (row&7) swizzle) ----
    {
        const size_t aoff = (size_t)(b*N_ + jb)*H_;
        const size_t boff = (size_t)b*N_*2*H_ + (size_t)cb*H_;
        const __nv_bfloat16* src[4] = { g_hr_hi + aoff, g_hr_lo + aoff,
                                        g_t_hi  + boff, g_t_lo  + boff };
        #pragma unroll
        for (int s = 0; s < 4; s++) {
            #pragma unroll
            for (int l = 0; l < 8; l++) {
                int idx = tid + l*256;             // 0..2047
                int r = idx >> 4, q = idx & 15;
                float4 v = *reinterpret_cast<const float4*>(src[s] + r*H_ + q*8);
                *reinterpret_cast<float4*>(smem + s*SLAB_ + (r << 8)
                                           + ((q ^ (r & 7)) << 4)) = v;
            }
        }
    }
    __syncthreads();

    // ---- warp coordinates ----
    const int wj = wid >> 2;                       // 0..1 : j offset /64
    const int wc = wid & 3;                        // 0..3 : c offset /32
    const uint32_t swz  = (uint32_t)(lid & 7);
    const uint32_t rowA = (uint32_t)(wj*64 + (lid & 15));
    const uint32_t selA = (uint32_t)(lid >> 4);               // k-chunk select
    const uint32_t rowB = (uint32_t)(wc*32 + (lid & 7) + ((lid >> 4) << 3));
    const uint32_t selB = (uint32_t)((lid >> 3) & 1);

    float acc[4][4][4];
    #pragma unroll
    for (int mt = 0; mt < 4; mt++)
        #pragma unroll
        for (int nt = 0; nt < 4; nt++)
            #pragma unroll
            for (int e = 0; e < 4; e++) acc[mt][nt][e] = 0.0f;

    #pragma unroll
    for (int kk = 0; kk < 8; kk++) {               // 8 x k16
        const uint32_t qa = ((((uint32_t)(kk*2) + selA) ^ swz) << 4);
        const uint32_t qb = ((((uint32_t)(kk*2) + selB) ^ swz) << 4);

        uint32_t ahi[4][4], alo[4][4];
        #pragma unroll
        for (int mt = 0; mt < 4; mt++) {
            uint32_t rbase = (rowA + mt*16) << 8;
            LDSM_X4(ahi[mt][0], ahi[mt][1], ahi[mt][2], ahi[mt][3], sAhi + rbase + qa);
            LDSM_X4(alo[mt][0], alo[mt][1], alo[mt][2], alo[mt][3], sAlo + rbase + qa);
        }
        uint32_t bhi[2][4], blo[2][4];
        #pragma unroll
        for (int bp = 0; bp < 2; bp++) {
            uint32_t rbase = (rowB + bp*16) << 8;
            LDSM_X4(bhi[bp][0], bhi[bp][1], bhi[bp][2], bhi[bp][3], sBhi + rbase + qb);
            LDSM_X4(blo[bp][0], blo[bp][1], blo[bp][2], blo[bp][3], sBlo + rbase + qb);
        }
        #pragma unroll
        for (int mt = 0; mt < 4; mt++)
            #pragma unroll
            for (int nt = 0; nt < 4; nt++) {
                const int bp = nt >> 1, be = (nt & 1)*2;
                MMA16816(acc[mt][nt], ahi[mt], bhi[bp][be], bhi[bp][be+1]);  // hi*hi
                MMA16816(acc[mt][nt], ahi[mt], blo[bp][be], blo[bp][be+1]);  // hi*lo
                MMA16816(acc[mt][nt], alo[mt], bhi[bp][be], bhi[bp][be+1]);  // lo*hi
            }
    }

    // ---- epilogue: thread cols = (k0,k1) of one i -> float2 stores ----
    const float bb0 = bbil[0];
    const float bb1 = bbil[1];
    const int jg = jb + wj*64 + (lid >> 2);
    const int ig = ((cb + wc*32) >> 1) + (lid & 3);
    #pragma unroll
    for (int mt = 0; mt < 4; mt++) {
        const int j0 = jg + mt*16;
        #pragma unroll
        for (int nt = 0; nt < 4; nt++) {
            const int i0 = ig + nt*4;
            float* o = out + ((size_t)(b*N_ + i0)*N_)*2;
            float2 v0, v1;
            v0.x = acc[mt][nt][0] + bb0;  v0.y = acc[mt][nt][1] + bb1;
            v1.x = acc[mt][nt][2] + bb0;  v1.y = acc[mt][nt][3] + bb1;
            *reinterpret_cast<float2*>(o + (size_t)j0*2)       = v0;
            *reinterpret_cast<float2*>(o + (size_t)(j0 + 8)*2) = v1;
        }
    }
}

// ---------------------------------------------------------------------------
extern "C" void kernel_launch(void* const* d_in, const int* in_sizes, int n_in,
                              void* d_out, int out_size)
{
    const float* x    = (const float*)d_in[0];
    const float* Wl   = (const float*)d_in[1];
    const float* bl   = (const float*)d_in[2];
    const float* Wr   = (const float*)d_in[3];
    const float* br   = (const float*)d_in[4];
    const float* Wbil = (const float*)d_in[5];
    const float* bbil = (const float*)d_in[6];
    float* out = (float*)d_out;
    (void)in_sizes; (void)n_in; (void)out_size;

    cudaFuncSetAttribute(pair_kernel,
                         cudaFuncAttributeMaxDynamicSharedMemorySize, SM_PAIR);

    transpose_w_kernel<<<(CTXF_*H_ + 255)/256, 256>>>(Wl, Wr);
    prep_kernel<<<B_*N_/TI_, 128>>>(x, bl, br, Wbil);
    pair_kernel<<<dim3(2*N_/PC_, N_/PJ_, B_), 256, SM_PAIR>>>(bbil, out);
}

// round 11
// speedup vs baseline: 2.3040x; 2.1263x over previous
#include <cuda_runtime.h>
#include <cuda_fp16.h>
#include <cstdint>

#define B_    8
#define N_    1024
#define NIN_  64
#define H_    128
#define CTXF_ 192
#define TI_   8

// pair-kernel tiling: 128 j  x  128 c(=i*2+k)  x  K=128 g per CTA
#define PJ_   128
#define PC_   128

// ---------------------------------------------------------------------------
// Scratch (device globals; no allocation allowed)
// ---------------------------------------------------------------------------
__device__ __half g_hr[B_*N_*H_];      // [B,N,H]    fp16 relu'd right hidden
__device__ __half g_t [B_*N_*2*H_];    // [B,N,2,H]  fp16 t = hl @ W_bil
__device__ float  g_Wlt[CTXF_*H_];     // W_l^T  [f][h]
__device__ float  g_Wrt[CTXF_*H_];     // W_r^T  [f][h]

// ---------------------------------------------------------------------------
// PTX helpers (plain sm_103-legal: ldmatrix + mma.sync, NO tcgen05)
// ---------------------------------------------------------------------------
__device__ __forceinline__ uint32_t smem_u32(const void* p) {
    uint32_t a;
    asm("{ .reg .u64 t; cvta.to.shared.u64 t, %1; cvt.u32.u64 %0, t; }" : "=r"(a) : "l"(p));
    return a;
}

#define LDSM_X4(r0, r1, r2, r3, addr) \
    asm volatile("ldmatrix.sync.aligned.m8n8.x4.shared.b16 {%0,%1,%2,%3}, [%4];" \
        : "=r"(r0), "=r"(r1), "=r"(r2), "=r"(r3) : "r"(addr))

#define MMA16816F16(d, a, b0, b1) \
    asm volatile("mma.sync.aligned.m16n8k16.row.col.f32.f16.f16.f32 " \
        "{%0,%1,%2,%3},{%4,%5,%6,%7},{%8,%9},{%0,%1,%2,%3};" \
        : "+f"((d)[0]), "+f"((d)[1]), "+f"((d)[2]), "+f"((d)[3]) \
        : "r"((a)[0]), "r"((a)[1]), "r"((a)[2]), "r"((a)[3]), "r"(b0), "r"(b1))

// ---------------------------------------------------------------------------
// One-time weight transpose ([h][f] -> [f][h]) for coalesced MLP reads
// ---------------------------------------------------------------------------
__global__ void transpose_w_kernel(const float* __restrict__ Wl,
                                   const float* __restrict__ Wr)
{
    int idx = blockIdx.x * 256 + threadIdx.x;
    if (idx < CTXF_*H_) {
        int f = idx >> 7, h = idx & 127;
        g_Wlt[idx] = Wl[h*CTXF_ + f];
        g_Wrt[idx] = Wr[h*CTXF_ + f];
    }
}

// ---------------------------------------------------------------------------
// Prep: context expansion + MLP + t = hl @ W_bil; outputs fp16.
// One block = TI_=8 sequence positions. 128 threads (thread = h, then = g).
// ---------------------------------------------------------------------------
__global__ void __launch_bounds__(128) prep_kernel(
    const float* __restrict__ x,
    const float* __restrict__ bl,
    const float* __restrict__ br,
    const float* __restrict__ Wbil)
{
    __shared__ __align__(16) float sx[(TI_+2)*NIN_];   // rows i0-1 .. i0+TI_
    __shared__ __align__(16) float s_hl[TI_][H_];

    const int blk = blockIdx.x;
    const int b   = blk >> 7;                // N/TI = 128 blocks per batch
    const int i0  = (blk & 127) * TI_;
    const int tid = threadIdx.x;

    #pragma unroll
    for (int l = 0; l < 5; l++) {
        int idx = tid + l*128;               // 0..639
        int r   = idx >> 6;                  // 0..9
        int row = i0 - 1 + r;
        float v = 0.0f;
        if (row >= 0 && row < N_) v = x[(b*N_ + row)*NIN_ + (idx & 63)];
        sx[idx] = v;
    }
    __syncthreads();

    const int h = tid;
    float accl[TI_], accr[TI_];
    {
        float blv = bl[h], brv = br[h];
        #pragma unroll
        for (int r = 0; r < TI_; r++) { accl[r] = blv; accr[r] = brv; }
    }

    const float4* sx4 = reinterpret_cast<const float4*>(sx);

    #pragma unroll 1
    for (int seg = 0; seg < 3; seg++) {
        const int dl = (seg == 0) ? 0 : (seg == 1 ? -1 : 1);
        const int dr = -dl;
        #pragma unroll 2
        for (int f4 = 0; f4 < 16; f4++) {
            const int fbase = seg*64 + f4*4;
            float wl0 = g_Wlt[(fbase+0)*H_ + h];
            float wl1 = g_Wlt[(fbase+1)*H_ + h];
            float wl2 = g_Wlt[(fbase+2)*H_ + h];
            float wl3 = g_Wlt[(fbase+3)*H_ + h];
            float wr0 = g_Wrt[(fbase+0)*H_ + h];
            float wr1 = g_Wrt[(fbase+1)*H_ + h];
            float wr2 = g_Wrt[(fbase+2)*H_ + h];
            float wr3 = g_Wrt[(fbase+3)*H_ + h];
            #pragma unroll
            for (int r = 0; r < TI_; r++) {
                float4 xl = sx4[(r+1+dl)*16 + f4];
                float4 xr = sx4[(r+1+dr)*16 + f4];
                accl[r] = fmaf(wl0, xl.x, accl[r]);
                accl[r] = fmaf(wl1, xl.y, accl[r]);
                accl[r] = fmaf(wl2, xl.z, accl[r]);
                accl[r] = fmaf(wl3, xl.w, accl[r]);
                accr[r] = fmaf(wr0, xr.x, accr[r]);
                accr[r] = fmaf(wr1, xr.y, accr[r]);
                accr[r] = fmaf(wr2, xr.z, accr[r]);
                accr[r] = fmaf(wr3, xr.w, accr[r]);
            }
        }
    }

    #pragma unroll
    for (int r = 0; r < TI_; r++) {
        s_hl[r][h] = fmaxf(accl[r], 0.0f);
        g_hr[(size_t)(b*N_ + i0 + r)*H_ + h] = __float2half(fmaxf(accr[r], 0.0f));
    }
    __syncthreads();

    // t[k][r][g] = sum_h s_hl[r][h] * Wbil[k][h][g]; thread owns one g
    const int g = tid;
    float t0[TI_], t1[TI_];
    #pragma unroll
    for (int r = 0; r < TI_; r++) { t0[r] = 0.f; t1[r] = 0.f; }

    #pragma unroll 2
    for (int h0 = 0; h0 < H_; h0 += 4) {
        float w0[4], w1[4];
        #pragma unroll
        for (int hh = 0; hh < 4; hh++) {
            w0[hh] = Wbil[(h0+hh)*H_ + g];
            w1[hh] = Wbil[H_*H_ + (h0+hh)*H_ + g];
        }
        #pragma unroll
        for (int r = 0; r < TI_; r++) {
            float4 hv = *reinterpret_cast<const float4*>(&s_hl[r][h0]);
            t0[r] = fmaf(hv.x, w0[0], t0[r]);  t1[r] = fmaf(hv.x, w1[0], t1[r]);
            t0[r] = fmaf(hv.y, w0[1], t0[r]);  t1[r] = fmaf(hv.y, w1[1], t1[r]);
            t0[r] = fmaf(hv.z, w0[2], t0[r]);  t1[r] = fmaf(hv.z, w1[2], t1[r]);
            t0[r] = fmaf(hv.w, w0[3], t0[r]);  t1[r] = fmaf(hv.w, w1[3], t1[r]);
        }
    }
    #pragma unroll
    for (int r = 0; r < TI_; r++) {
        size_t rowbase = (size_t)(b*N_ + i0 + r)*2*H_;
        g_t[rowbase +      g] = __float2half(t0[r]);
        g_t[rowbase + H_ + g] = __float2half(t1[r]);
    }
}

// ---------------------------------------------------------------------------
// Pairwise GEMM, fp16 single-pass HMMA (fp32 accum):
//   D[j][c] = sum_g hr[b,jb+j,g] * t[b, cb+c rows, g]   (c = i*2+k)
//   Single smem stage: 2 slabs of 128 rows x 256B (swizzled) = 64 KB
//   -> 2 CTAs/SM. 8 warps = 2(j) x 4(c); warp tile 64x32; per k-step:
//   6 LDSM -> 16 MMA.
// ---------------------------------------------------------------------------
#define SLAB_   (PJ_*256)          // 32 KB
#define SM_PAIR (2*SLAB_)          // 65536

__global__ void __launch_bounds__(256, 2) pair_kernel(
    const float* __restrict__ bbil, float* __restrict__ out)
{
    extern __shared__ __align__(16) char smem[];
    const uint32_t sA = smem_u32(smem);            // A: hr tile
    const uint32_t sB = sA + SLAB_;                // B: t tile

    const int tid = threadIdx.x;
    const int wid = tid >> 5;
    const int lid = tid & 31;
    const int b   = blockIdx.z;
    const int cb  = blockIdx.x * PC_;              // c-row base (i*2+k space)
    const int jb  = blockIdx.y * PJ_;

    // ---- cooperative tile loads (16B chunks, q ^ (row&7) swizzle) ----
    {
        const __half* Asrc = g_hr + (size_t)(b*N_ + jb)*H_;
        const __half* Bsrc = g_t  + (size_t)b*N_*2*H_ + (size_t)cb*H_;
        #pragma unroll
        for (int l = 0; l < 8; l++) {
            int idx = tid + l*256;                 // 0..2047
            int r = idx >> 4, q = idx & 15;
            float4 v = *reinterpret_cast<const float4*>(Asrc + r*H_ + q*8);
            *reinterpret_cast<float4*>(smem + (r << 8) + ((q ^ (r & 7)) << 4)) = v;
        }
        #pragma unroll
        for (int l = 0; l < 8; l++) {
            int idx = tid + l*256;
            int r = idx >> 4, q = idx & 15;
            float4 v = *reinterpret_cast<const float4*>(Bsrc + r*H_ + q*8);
            *reinterpret_cast<float4*>(smem + SLAB_ + (r << 8)
                                       + ((q ^ (r & 7)) << 4)) = v;
        }
    }
    __syncthreads();

    // ---- warp coordinates ----
    const int wj = wid >> 2;                       // 0..1 : j offset /64
    const int wc = wid & 3;                        // 0..3 : c offset /32
    const uint32_t swz  = (uint32_t)(lid & 7);
    const uint32_t rowA = (uint32_t)(wj*64 + (lid & 15));
    const uint32_t selA = (uint32_t)(lid >> 4);               // k-chunk select
    const uint32_t rowB = (uint32_t)(wc*32 + (lid & 7) + ((lid >> 4) << 3));
    const uint32_t selB = (uint32_t)((lid >> 3) & 1);

    float acc[4][4][4];
    #pragma unroll
    for (int mt = 0; mt < 4; mt++)
        #pragma unroll
        for (int nt = 0; nt < 4; nt++)
            #pragma unroll
            for (int e = 0; e < 4; e++) acc[mt][nt][e] = 0.0f;

    #pragma unroll
    for (int kk = 0; kk < 8; kk++) {               // 8 x k16
        const uint32_t qa = ((((uint32_t)(kk*2) + selA) ^ swz) << 4);
        const uint32_t qb = ((((uint32_t)(kk*2) + selB) ^ swz) << 4);

        uint32_t a[4][4];
        #pragma unroll
        for (int mt = 0; mt < 4; mt++) {
            uint32_t rbase = (rowA + mt*16) << 8;
            LDSM_X4(a[mt][0], a[mt][1], a[mt][2], a[mt][3], sA + rbase + qa);
        }
        uint32_t bf[2][4];
        #pragma unroll
        for (int bp = 0; bp < 2; bp++) {
            uint32_t rbase = (rowB + bp*16) << 8;
            LDSM_X4(bf[bp][0], bf[bp][1], bf[bp][2], bf[bp][3], sB + rbase + qb);
        }
        #pragma unroll
        for (int mt = 0; mt < 4; mt++)
            #pragma unroll
            for (int nt = 0; nt < 4; nt++) {
                const int bp = nt >> 1, be = (nt & 1)*2;
                MMA16816F16(acc[mt][nt], a[mt], bf[bp][be], bf[bp][be+1]);
            }
    }

    // ---- epilogue: thread cols = (k0,k1) of one i -> float2 stores ----
    const float bb0 = bbil[0];
    const float bb1 = bbil[1];
    const int jg = jb + wj*64 + (lid >> 2);
    const int ig = ((cb + wc*32) >> 1) + (lid & 3);
    #pragma unroll
    for (int mt = 0; mt < 4; mt++) {
        const int j0 = jg + mt*16;
        #pragma unroll
        for (int nt = 0; nt < 4; nt++) {
            const int i0 = ig + nt*4;
            float* o = out + ((size_t)(b*N_ + i0)*N_)*2;
            float2 v0, v1;
            v0.x = acc[mt][nt][0] + bb0;  v0.y = acc[mt][nt][1] + bb1;
            v1.x = acc[mt][nt][2] + bb0;  v1.y = acc[mt][nt][3] + bb1;
            *reinterpret_cast<float2*>(o + (size_t)j0*2)       = v0;
            *reinterpret_cast<float2*>(o + (size_t)(j0 + 8)*2) = v1;
        }
    }
}

// ---------------------------------------------------------------------------
extern "C" void kernel_launch(void* const* d_in, const int* in_sizes, int n_in,
                              void* d_out, int out_size)
{
    const float* x    = (const float*)d_in[0];
    const float* Wl   = (const float*)d_in[1];
    const float* bl   = (const float*)d_in[2];
    const float* Wr   = (const float*)d_in[3];
    const float* br   = (const float*)d_in[4];
    const float* Wbil = (const float*)d_in[5];
    const float* bbil = (const float*)d_in[6];
    float* out = (float*)d_out;
    (void)in_sizes; (void)n_in; (void)out_size;

    cudaFuncSetAttribute(pair_kernel,
                         cudaFuncAttributeMaxDynamicSharedMemorySize, SM_PAIR);

    transpose_w_kernel<<<(CTXF_*H_ + 255)/256, 256>>>(Wl, Wr);
    prep_kernel<<<B_*N_/TI_, 128>>>(x, bl, br, Wbil);
    pair_kernel<<<dim3(2*N_/PC_, N_/PJ_, B_), 256, SM_PAIR>>>(bbil, out);
}

// round 16
// speedup vs baseline: 3.9345x; 1.7077x over previous
#include <cuda_runtime.h>
#include <cuda_fp16.h>
#include <cstdint>

#define B_    8
#define N_    1024
#define NIN_  64
#define H_    128

#define PJ_   128
#define PC_   128

// ---------------------------------------------------------------------------
// Scratch (device globals; no allocation allowed)
// ---------------------------------------------------------------------------
__device__ __half g_hr   [B_*N_*H_];      // [B,N,H]   fp16 relu'd right hidden
__device__ __half g_hl_hi[B_*N_*H_];      // hl hi/lo pair (22-bit effective)
__device__ __half g_hl_lo[B_*N_*H_];
__device__ __half g_t    [B_*N_*2*H_];    // [B,N,2,H] fp16 t = hl @ W_bil
__device__ __half g_Wc   [256*192];       // combined+permuted MLP weights, k-major
__device__ __half g_Wbc  [256*128];       // Wbil rearranged [n=k*128+g][h], k-major

// ---------------------------------------------------------------------------
// PTX helpers (plain sm_103-legal: ldmatrix + mma.sync, NO tcgen05)
// ---------------------------------------------------------------------------
__device__ __forceinline__ uint32_t smem_u32(const void* p) {
    uint32_t a;
    asm("{ .reg .u64 t; cvta.to.shared.u64 t, %1; cvt.u32.u64 %0, t; }" : "=r"(a) : "l"(p));
    return a;
}

#define LDSM_X4(r0, r1, r2, r3, addr) \
    asm volatile("ldmatrix.sync.aligned.m8n8.x4.shared.b16 {%0,%1,%2,%3}, [%4];" \
        : "=r"(r0), "=r"(r1), "=r"(r2), "=r"(r3) : "r"(addr))

#define MMA16816F16(d, a, b0, b1) \
    asm volatile("mma.sync.aligned.m16n8k16.row.col.f32.f16.f16.f32 " \
        "{%0,%1,%2,%3},{%4,%5,%6,%7},{%8,%9},{%0,%1,%2,%3};" \
        : "+f"((d)[0]), "+f"((d)[1]), "+f"((d)[2]), "+f"((d)[3]) \
        : "r"((a)[0]), "r"((a)[1]), "r"((a)[2]), "r"((a)[3]), "r"(b0), "r"(b1))

__device__ __forceinline__ __half2 split_hi2(float v0, float v1) {
    return __halves2half2(__float2half(v0), __float2half(v1));
}
__device__ __forceinline__ __half2 split_lo2(float v0, float v1) {
    __half h0 = __float2half(v0), h1 = __float2half(v1);
    return __halves2half2(__float2half(v0 - __half2float(h0)),
                          __float2half(v1 - __half2float(h1)));
}

// ---------------------------------------------------------------------------
// Setup: build combined MLP weight [256][192] (k-major, fp16) and the
// rearranged bilinear weight [256][128].
//   A features f: [0,64)=x[i-1], [64,128)=x[i], [128,192)=x[i+1]
//   n<128 (hl, Wl segs: x[i]->0:64, x[i-1]->64:128, x[i+1]->128:192)
//   n>=128 (hr, Wr segs: x[i]->0:64, x[i+1]->64:128, x[i-1]->128:192)
// ---------------------------------------------------------------------------
__global__ void setup_kernel(const float* __restrict__ Wl,
                             const float* __restrict__ Wr,
                             const float* __restrict__ Wbil)
{
    int idx = blockIdx.x * 256 + threadIdx.x;
    if (idx < 256*192) {
        int n = idx / 192, f = idx % 192;
        float v;
        if (n < 128) {
            v = (f < 64)  ? Wl[n*192 + 64 + f]
              : (f < 128) ? Wl[n*192 + f - 64]
                          : Wl[n*192 + f];
        } else {
            int h = n - 128;
            v = (f < 64)  ? Wr[h*192 + 128 + f]
                          : Wr[h*192 + f - 64];
        }
        g_Wc[idx] = __float2half(v);
    } else if (idx < 256*192 + 256*128) {
        int j = idx - 256*192;
        int n = j >> 7, hh = j & 127;
        g_Wbc[j] = __float2half(Wbil[(n >> 7)*H_*H_ + hh*H_ + (n & 127)]);
    }
}

// ---------------------------------------------------------------------------
// GEMM1: [hl|hr] = relu(A @ W_c^T + b),  per CTA: 128 rows x 128 cols, K=192.
//   A (x context window) split hi/lo fp16 -> error from W rounding only.
//   Row stride 384B (24 x 16B chunks); 384 % 128 == 0 so q^(r&7) swizzle
//   stays conflict-free for ldmatrix.
//   ct=0 -> hl (bias bl, relu, hi/lo split out), ct=1 -> hr (bias br, fp16).
// ---------------------------------------------------------------------------
#define G1_STR  384
#define G1_SLAB (128*G1_STR)               // 48 KB
#define SM_G1   (3*G1_SLAB)                // 147456

__global__ void __launch_bounds__(256, 1) gemm1_kernel(
    const float* __restrict__ x,
    const float* __restrict__ bl,
    const float* __restrict__ br)
{
    extern __shared__ __align__(16) char smem[];
    const uint32_t sAhi = smem_u32(smem);
    const uint32_t sAlo = sAhi + G1_SLAB;
    const uint32_t sB   = sAhi + 2*G1_SLAB;

    const int tid = threadIdx.x;
    const int wid = tid >> 5;
    const int lid = tid & 31;
    const int ct  = blockIdx.x;            // 0: hl, 1: hr
    const int rt  = blockIdx.y;            // row tile (128 rows)
    const int b   = rt >> 3;
    const int i0  = (rt & 7) * 128;

    // ---- A: assemble context window, split hi/lo, swizzled ----
    #pragma unroll
    for (int l = 0; l < 24; l++) {
        int idx = tid + l*256;             // 0..6143 = 128 rows x 48 float4
        int r = idx / 48, f4 = idx % 48;
        int f  = f4 * 4;
        int df = (f < 64) ? -1 : (f < 128) ? 0 : 1;
        int fc = f & 63;
        int i  = i0 + r + df;
        float4 v = make_float4(0.f, 0.f, 0.f, 0.f);
        if ((unsigned)i < N_)
            v = *reinterpret_cast<const float4*>(x + (size_t)(b*N_ + i)*NIN_ + fc);
        uint32_t off = (uint32_t)(r*G1_STR + (((f4 >> 1) ^ (r & 7)) << 4) + (f4 & 1)*8);
        __half2* dh = reinterpret_cast<__half2*>(smem + (sAhi - sAhi) + off); // A_hi at slab 0
        dh[0] = split_hi2(v.x, v.y);  dh[1] = split_hi2(v.z, v.w);
        __half2* dl = reinterpret_cast<__half2*>(smem + G1_SLAB + off);
        dl[0] = split_lo2(v.x, v.y);  dl[1] = split_lo2(v.z, v.w);
    }
    // ---- B: 128 weight rows x 24 chunks ----
    #pragma unroll
    for (int l = 0; l < 12; l++) {
        int idx = tid + l*256;             // 0..3071
        int n = idx / 24, q = idx % 24;
        float4 v = *reinterpret_cast<const float4*>(g_Wc + (size_t)(ct*128 + n)*192 + q*8);
        *reinterpret_cast<float4*>(smem + 2*G1_SLAB + n*G1_STR + ((q ^ (n & 7)) << 4)) = v;
    }
    __syncthreads();

    const int wj = wid >> 2;
    const int wc = wid & 3;
    const uint32_t swz  = (uint32_t)(lid & 7);
    const uint32_t rowA = (uint32_t)(wj*64 + (lid & 15));
    const uint32_t selA = (uint32_t)(lid >> 4);
    const uint32_t rowB = (uint32_t)(wc*32 + (lid & 7) + ((lid >> 4) << 3));
    const uint32_t selB = (uint32_t)((lid >> 3) & 1);

    float acc[4][4][4];
    #pragma unroll
    for (int mt = 0; mt < 4; mt++)
        #pragma unroll
        for (int nt = 0; nt < 4; nt++)
            #pragma unroll
            for (int e = 0; e < 4; e++) acc[mt][nt][e] = 0.0f;

    #pragma unroll
    for (int kk = 0; kk < 12; kk++) {
        const uint32_t qa = ((((uint32_t)(kk*2) + selA) ^ swz) << 4);
        const uint32_t qb = ((((uint32_t)(kk*2) + selB) ^ swz) << 4);
        uint32_t ahi[4][4], alo[4][4];
        #pragma unroll
        for (int mt = 0; mt < 4; mt++) {
            uint32_t rb = (rowA + mt*16)*G1_STR;
            LDSM_X4(ahi[mt][0], ahi[mt][1], ahi[mt][2], ahi[mt][3], sAhi + rb + qa);
            LDSM_X4(alo[mt][0], alo[mt][1], alo[mt][2], alo[mt][3], sAlo + rb + qa);
        }
        uint32_t bf[2][4];
        #pragma unroll
        for (int bp = 0; bp < 2; bp++) {
            uint32_t rb = (rowB + bp*16)*G1_STR;
            LDSM_X4(bf[bp][0], bf[bp][1], bf[bp][2], bf[bp][3], sB + rb + qb);
        }
        #pragma unroll
        for (int mt = 0; mt < 4; mt++)
            #pragma unroll
            for (int nt = 0; nt < 4; nt++) {
                const int bp = nt >> 1, be = (nt & 1)*2;
                MMA16816F16(acc[mt][nt], ahi[mt], bf[bp][be], bf[bp][be+1]);
                MMA16816F16(acc[mt][nt], alo[mt], bf[bp][be], bf[bp][be+1]);
            }
    }

    // ---- epilogue ----
    const int r0 = wj*64 + (lid >> 2);
    const int n0 = wc*32 + (lid & 3)*2;
    const size_t gbase = (size_t)rt * 128;
    #pragma unroll
    for (int mt = 0; mt < 4; mt++) {
        #pragma unroll
        for (int nt = 0; nt < 4; nt++) {
            const int n = n0 + nt*8;
            const size_t ra = gbase + r0 + mt*16;
            if (ct == 0) {
                float b0v = bl[n], b1v = bl[n+1];
                float v0 = fmaxf(acc[mt][nt][0] + b0v, 0.f);
                float v1 = fmaxf(acc[mt][nt][1] + b1v, 0.f);
                float v2 = fmaxf(acc[mt][nt][2] + b0v, 0.f);
                float v3 = fmaxf(acc[mt][nt][3] + b1v, 0.f);
                *reinterpret_cast<__half2*>(g_hl_hi + ra*H_ + n)       = split_hi2(v0, v1);
                *reinterpret_cast<__half2*>(g_hl_lo + ra*H_ + n)       = split_lo2(v0, v1);
                *reinterpret_cast<__half2*>(g_hl_hi + (ra+8)*H_ + n)   = split_hi2(v2, v3);
                *reinterpret_cast<__half2*>(g_hl_lo + (ra+8)*H_ + n)   = split_lo2(v2, v3);
            } else {
                float b0v = br[n], b1v = br[n+1];
                float v0 = fmaxf(acc[mt][nt][0] + b0v, 0.f);
                float v1 = fmaxf(acc[mt][nt][1] + b1v, 0.f);
                float v2 = fmaxf(acc[mt][nt][2] + b0v, 0.f);
                float v3 = fmaxf(acc[mt][nt][3] + b1v, 0.f);
                *reinterpret_cast<__half2*>(g_hr + ra*H_ + n)     = split_hi2(v0, v1);
                *reinterpret_cast<__half2*>(g_hr + (ra+8)*H_ + n) = split_hi2(v2, v3);
            }
        }
    }
}

// ---------------------------------------------------------------------------
// GEMM2: t = hl @ Wbc^T, per CTA 128 rows x 128 cols, K=128.
//   hl as hi/lo pair -> W-rounding-only error. Output col n_glob = k*128+g
//   lands at g_t[row*256 + n_glob] directly.
// ---------------------------------------------------------------------------
#define G2_SLAB (128*256)                  // 32 KB
#define SM_G2   (3*G2_SLAB)                // 98304

__global__ void __launch_bounds__(256, 2) gemm2_kernel()
{
    extern __shared__ __align__(16) char smem[];
    const uint32_t sAhi = smem_u32(smem);
    const uint32_t sAlo = sAhi + G2_SLAB;
    const uint32_t sB   = sAhi + 2*G2_SLAB;

    const int tid = threadIdx.x;
    const int wid = tid >> 5;
    const int lid = tid & 31;
    const int ct  = blockIdx.x;
    const int rt  = blockIdx.y;

    const size_t arow = (size_t)rt * 128;
    #pragma unroll
    for (int l = 0; l < 8; l++) {
        int idx = tid + l*256;             // 0..2047
        int r = idx >> 4, q = idx & 15;
        uint32_t off = (uint32_t)((r << 8) + ((q ^ (r & 7)) << 4));
        float4 vh = *reinterpret_cast<const float4*>(g_hl_hi + (arow + r)*H_ + q*8);
        *reinterpret_cast<float4*>(smem + off) = vh;
        float4 vl = *reinterpret_cast<const float4*>(g_hl_lo + (arow + r)*H_ + q*8);
        *reinterpret_cast<float4*>(smem + G2_SLAB + off) = vl;
    }
    #pragma unroll
    for (int l = 0; l < 8; l++) {
        int idx = tid + l*256;
        int n = idx >> 4, q = idx & 15;
        float4 v = *reinterpret_cast<const float4*>(g_Wbc + (size_t)(ct*128 + n)*H_ + q*8);
        *reinterpret_cast<float4*>(smem + 2*G2_SLAB + (n << 8) + ((q ^ (n & 7)) << 4)) = v;
    }
    __syncthreads();

    const int wj = wid >> 2;
    const int wc = wid & 3;
    const uint32_t swz  = (uint32_t)(lid & 7);
    const uint32_t rowA = (uint32_t)(wj*64 + (lid & 15));
    const uint32_t selA = (uint32_t)(lid >> 4);
    const uint32_t rowB = (uint32_t)(wc*32 + (lid & 7) + ((lid >> 4) << 3));
    const uint32_t selB = (uint32_t)((lid >> 3) & 1);

    float acc[4][4][4];
    #pragma unroll
    for (int mt = 0; mt < 4; mt++)
        #pragma unroll
        for (int nt = 0; nt < 4; nt++)
            #pragma unroll
            for (int e = 0; e < 4; e++) acc[mt][nt][e] = 0.0f;

    #pragma unroll
    for (int kk = 0; kk < 8; kk++) {
        const uint32_t qa = ((((uint32_t)(kk*2) + selA) ^ swz) << 4);
        const uint32_t qb = ((((uint32_t)(kk*2) + selB) ^ swz) << 4);
        uint32_t ahi[4][4], alo[4][4];
        #pragma unroll
        for (int mt = 0; mt < 4; mt++) {
            uint32_t rb = (rowA + mt*16) << 8;
            LDSM_X4(ahi[mt][0], ahi[mt][1], ahi[mt][2], ahi[mt][3], sAhi + rb + qa);
            LDSM_X4(alo[mt][0], alo[mt][1], alo[mt][2], alo[mt][3], sAlo + rb + qa);
        }
        uint32_t bf[2][4];
        #pragma unroll
        for (int bp = 0; bp < 2; bp++) {
            uint32_t rb = (rowB + bp*16) << 8;
            LDSM_X4(bf[bp][0], bf[bp][1], bf[bp][2], bf[bp][3], sB + rb + qb);
        }
        #pragma unroll
        for (int mt = 0; mt < 4; mt++)
            #pragma unroll
            for (int nt = 0; nt < 4; nt++) {
                const int bp = nt >> 1, be = (nt & 1)*2;
                MMA16816F16(acc[mt][nt], ahi[mt], bf[bp][be], bf[bp][be+1]);
                MMA16816F16(acc[mt][nt], alo[mt], bf[bp][be], bf[bp][be+1]);
            }
    }

    const int r0 = wj*64 + (lid >> 2);
    const int n0 = ct*128 + wc*32 + (lid & 3)*2;
    #pragma unroll
    for (int mt = 0; mt < 4; mt++) {
        #pragma unroll
        for (int nt = 0; nt < 4; nt++) {
            const int n = n0 + nt*8;
            const size_t ra = arow + r0 + mt*16;
            *reinterpret_cast<__half2*>(g_t + ra*256 + n) =
                split_hi2(acc[mt][nt][0], acc[mt][nt][1]);
            *reinterpret_cast<__half2*>(g_t + (ra+8)*256 + n) =
                split_hi2(acc[mt][nt][2], acc[mt][nt][3]);
        }
    }
}

// ---------------------------------------------------------------------------
// Pairwise GEMM, fp16 single-pass HMMA (unchanged, verified)
// ---------------------------------------------------------------------------
#define SLAB_   (PJ_*256)
#define SM_PAIR (2*SLAB_)

__global__ void __launch_bounds__(256, 2) pair_kernel(
    const float* __restrict__ bbil, float* __restrict__ out)
{
    extern __shared__ __align__(16) char smem[];
    const uint32_t sA = smem_u32(smem);
    const uint32_t sB = sA + SLAB_;

    const int tid = threadIdx.x;
    const int wid = tid >> 5;
    const int lid = tid & 31;
    const int b   = blockIdx.z;
    const int cb  = blockIdx.x * PC_;
    const int jb  = blockIdx.y * PJ_;

    {
        const __half* Asrc = g_hr + (size_t)(b*N_ + jb)*H_;
        const __half* Bsrc = g_t  + (size_t)b*N_*2*H_ + (size_t)cb*H_;
        #pragma unroll
        for (int l = 0; l < 8; l++) {
            int idx = tid + l*256;
            int r = idx >> 4, q = idx & 15;
            float4 v = *reinterpret_cast<const float4*>(Asrc + r*H_ + q*8);
            *reinterpret_cast<float4*>(smem + (r << 8) + ((q ^ (r & 7)) << 4)) = v;
        }
        #pragma unroll
        for (int l = 0; l < 8; l++) {
            int idx = tid + l*256;
            int r = idx >> 4, q = idx & 15;
            float4 v = *reinterpret_cast<const float4*>(Bsrc + r*H_ + q*8);
            *reinterpret_cast<float4*>(smem + SLAB_ + (r << 8)
                                       + ((q ^ (r & 7)) << 4)) = v;
        }
    }
    __syncthreads();

    const int wj = wid >> 2;
    const int wc = wid & 3;
    const uint32_t swz  = (uint32_t)(lid & 7);
    const uint32_t rowA = (uint32_t)(wj*64 + (lid & 15));
    const uint32_t selA = (uint32_t)(lid >> 4);
    const uint32_t rowB = (uint32_t)(wc*32 + (lid & 7) + ((lid >> 4) << 3));
    const uint32_t selB = (uint32_t)((lid >> 3) & 1);

    float acc[4][4][4];
    #pragma unroll
    for (int mt = 0; mt < 4; mt++)
        #pragma unroll
        for (int nt = 0; nt < 4; nt++)
            #pragma unroll
            for (int e = 0; e < 4; e++) acc[mt][nt][e] = 0.0f;

    #pragma unroll
    for (int kk = 0; kk < 8; kk++) {
        const uint32_t qa = ((((uint32_t)(kk*2) + selA) ^ swz) << 4);
        const uint32_t qb = ((((uint32_t)(kk*2) + selB) ^ swz) << 4);
        uint32_t a[4][4];
        #pragma unroll
        for (int mt = 0; mt < 4; mt++) {
            uint32_t rb = (rowA + mt*16) << 8;
            LDSM_X4(a[mt][0], a[mt][1], a[mt][2], a[mt][3], sA + rb + qa);
        }
        uint32_t bf[2][4];
        #pragma unroll
        for (int bp = 0; bp < 2; bp++) {
            uint32_t rb = (rowB + bp*16) << 8;
            LDSM_X4(bf[bp][0], bf[bp][1], bf[bp][2], bf[bp][3], sB + rb + qb);
        }
        #pragma unroll
        for (int mt = 0; mt < 4; mt++)
            #pragma unroll
            for (int nt = 0; nt < 4; nt++) {
                const int bp = nt >> 1, be = (nt & 1)*2;
                MMA16816F16(acc[mt][nt], a[mt], bf[bp][be], bf[bp][be+1]);
            }
    }

    const float bb0 = bbil[0];
    const float bb1 = bbil[1];
    const int jg = jb + wj*64 + (lid >> 2);
    const int ig = ((cb + wc*32) >> 1) + (lid & 3);
    #pragma unroll
    for (int mt = 0; mt < 4; mt++) {
        const int j0 = jg + mt*16;
        #pragma unroll
        for (int nt = 0; nt < 4; nt++) {
            const int i0 = ig + nt*4;
            float* o = out + ((size_t)(b*N_ + i0)*N_)*2;
            float2 v0, v1;
            v0.x = acc[mt][nt][0] + bb0;  v0.y = acc[mt][nt][1] + bb1;
            v1.x = acc[mt][nt][2] + bb0;  v1.y = acc[mt][nt][3] + bb1;
            *reinterpret_cast<float2*>(o + (size_t)j0*2)       = v0;
            *reinterpret_cast<float2*>(o + (size_t)(j0 + 8)*2) = v1;
        }
    }
}

// ---------------------------------------------------------------------------
extern "C" void kernel_launch(void* const* d_in, const int* in_sizes, int n_in,
                              void* d_out, int out_size)
{
    const float* x    = (const float*)d_in[0];
    const float* Wl   = (const float*)d_in[1];
    const float* bl   = (const float*)d_in[2];
    const float* Wr   = (const float*)d_in[3];
    const float* br   = (const float*)d_in[4];
    const float* Wbil = (const float*)d_in[5];
    const float* bbil = (const float*)d_in[6];
    float* out = (float*)d_out;
    (void)in_sizes; (void)n_in; (void)out_size;

    cudaFuncSetAttribute(gemm1_kernel,
                         cudaFuncAttributeMaxDynamicSharedMemorySize, SM_G1);
    cudaFuncSetAttribute(gemm2_kernel,
                         cudaFuncAttributeMaxDynamicSharedMemorySize, SM_G2);
    cudaFuncSetAttribute(pair_kernel,
                         cudaFuncAttributeMaxDynamicSharedMemorySize, SM_PAIR);

    setup_kernel<<<(256*192 + 256*128 + 255)/256, 256>>>(Wl, Wr, Wbil);
    gemm1_kernel<<<dim3(2, B_*N_/128), 256, SM_G1>>>(x, bl, br);
    gemm2_kernel<<<dim3(2, B_*N_/128), 256, SM_G2>>>();
    pair_kernel<<<dim3(2*N_/PC_, N_/PJ_, B_), 256, SM_PAIR>>>(bbil, out);
}

// round 17
// speedup vs baseline: 4.1259x; 1.0486x over previous
#include <cuda_runtime.h>
#include <cuda_fp16.h>
#include <cstdint>

#define B_    8
#define N_    1024
#define NIN_  64
#define H_    128

#define PJ_   128
#define PC_   128

// ---------------------------------------------------------------------------
// Scratch (device globals; no allocation allowed)
// ---------------------------------------------------------------------------
__device__ __half g_hl[B_*N_*H_];         // [B,N,H]   fp16 relu'd left hidden
__device__ __half g_hr[B_*N_*H_];         // [B,N,H]   fp16 relu'd right hidden
__device__ __half g_t [B_*N_*2*H_];       // [B,N,2,H] fp16 t = hl @ W_bil

// ---------------------------------------------------------------------------
// PTX helpers (plain sm_103-legal: ldmatrix + mma.sync, NO tcgen05)
// ---------------------------------------------------------------------------
__device__ __forceinline__ uint32_t smem_u32(const void* p) {
    uint32_t a;
    asm("{ .reg .u64 t; cvta.to.shared.u64 t, %1; cvt.u32.u64 %0, t; }" : "=r"(a) : "l"(p));
    return a;
}

#define LDSM_X4(r0, r1, r2, r3, addr) \
    asm volatile("ldmatrix.sync.aligned.m8n8.x4.shared.b16 {%0,%1,%2,%3}, [%4];" \
        : "=r"(r0), "=r"(r1), "=r"(r2), "=r"(r3) : "r"(addr))

#define MMA16816F16(d, a, b0, b1) \
    asm volatile("mma.sync.aligned.m16n8k16.row.col.f32.f16.f16.f32 " \
        "{%0,%1,%2,%3},{%4,%5,%6,%7},{%8,%9},{%0,%1,%2,%3};" \
        : "+f"((d)[0]), "+f"((d)[1]), "+f"((d)[2]), "+f"((d)[3]) \
        : "r"((a)[0]), "r"((a)[1]), "r"((a)[2]), "r"((a)[3]), "r"(b0), "r"(b1))

__device__ __forceinline__ uint4 pack8(float4 a, float4 b) {
    __half2 h0 = __floats2half2_rn(a.x, a.y);
    __half2 h1 = __floats2half2_rn(a.z, a.w);
    __half2 h2 = __floats2half2_rn(b.x, b.y);
    __half2 h3 = __floats2half2_rn(b.z, b.w);
    uint4 u;
    u.x = *reinterpret_cast<uint32_t*>(&h0);
    u.y = *reinterpret_cast<uint32_t*>(&h1);
    u.z = *reinterpret_cast<uint32_t*>(&h2);
    u.w = *reinterpret_cast<uint32_t*>(&h3);
    return u;
}

// ---------------------------------------------------------------------------
// GEMM1: hl or hr = relu(A @ Wc^T + b); 64 rows x 128 cols, K=192 per CTA.
//   A features f: [0,64)=x[i-1], [64,128)=x[i], [128,192)=x[i+1], built and
//   converted to fp16 on the fly. W permuted/converted from fp32 on the fly:
//     ct=0 (hl): f<64 -> Wl[64+f], f<128 -> Wl[f-64], else Wl[f]
//     ct=1 (hr): f<64 -> Wr[128+f], else Wr[f-64]
//   8 warps in 2(m) x 4(n); warp tile 32x32; 12 k-steps; single fp16 pass.
//   Row stride 384B; q^(r&7) swizzle (XOR stays within 8-chunk group).
// ---------------------------------------------------------------------------
#define G1_STR 384
#define G1_SB  (64*G1_STR)                 // 24576
#define SM_G1  (G1_SB + 128*G1_STR)        // 73728

__global__ void __launch_bounds__(256) gemm1_kernel(
    const float* __restrict__ x,
    const float* __restrict__ Wl, const float* __restrict__ bl,
    const float* __restrict__ Wr, const float* __restrict__ br)
{
    extern __shared__ __align__(16) char smem[];
    const uint32_t sA = smem_u32(smem);
    const uint32_t sB = sA + G1_SB;

    const int tid = threadIdx.x;
    const int wid = tid >> 5;
    const int lid = tid & 31;
    const int ct  = blockIdx.x;            // 0: hl, 1: hr
    const int rt  = blockIdx.y;            // 64-row tile over B*N rows
    const int b   = rt >> 4;
    const int i0  = (rt & 15) * 64;

    // ---- A: 64 rows x 24 chunks (each = 8 fp32 -> 8 fp16) ----
    #pragma unroll
    for (int l = 0; l < 6; l++) {
        int idx = tid + l*256;             // 0..1535
        int r = idx / 24, q = idx % 24;
        int df = (q < 8) ? -1 : (q < 16) ? 0 : 1;
        int fc = (q & 7) * 8;
        int i  = i0 + r + df;
        float4 v0 = make_float4(0.f,0.f,0.f,0.f), v1 = v0;
        if ((unsigned)i < N_) {
            const float* p = x + (size_t)(b*N_ + i)*NIN_ + fc;
            v0 = *reinterpret_cast<const float4*>(p);
            v1 = *reinterpret_cast<const float4*>(p + 4);
        }
        *reinterpret_cast<uint4*>(smem + r*G1_STR + ((q ^ (r & 7)) << 4)) = pack8(v0, v1);
    }
    // ---- B: 128 weight rows x 24 chunks, permute+convert fp32->fp16 ----
    {
        const float* W = ct ? Wr : Wl;
        #pragma unroll
        for (int l = 0; l < 12; l++) {
            int idx = tid + l*256;         // 0..3071
            int n = idx / 24, q = idx % 24;
            int f0 = q * 8;
            int src = ct ? ((q < 8) ? 128 + f0 : f0 - 64)
                         : ((q < 8) ? 64 + f0 : (q < 16) ? f0 - 64 : f0);
            const float* p = W + (size_t)n*192 + src;
            float4 v0 = *reinterpret_cast<const float4*>(p);
            float4 v1 = *reinterpret_cast<const float4*>(p + 4);
            *reinterpret_cast<uint4*>(smem + G1_SB + n*G1_STR + ((q ^ (n & 7)) << 4)) = pack8(v0, v1);
        }
    }
    __syncthreads();

    const int wj = wid >> 2;               // 0..1 : m offset /32
    const int wc = wid & 3;                // 0..3 : n offset /32
    const uint32_t swz  = (uint32_t)(lid & 7);
    const uint32_t rowA = (uint32_t)(wj*32 + (lid & 15));
    const uint32_t selA = (uint32_t)(lid >> 4);
    const uint32_t rowB = (uint32_t)(wc*32 + (lid & 7) + ((lid >> 4) << 3));
    const uint32_t selB = (uint32_t)((lid >> 3) & 1);

    float acc[2][4][4];
    #pragma unroll
    for (int mt = 0; mt < 2; mt++)
        #pragma unroll
        for (int nt = 0; nt < 4; nt++)
            #pragma unroll
            for (int e = 0; e < 4; e++) acc[mt][nt][e] = 0.0f;

    #pragma unroll
    for (int kk = 0; kk < 12; kk++) {
        const uint32_t qa = ((((uint32_t)(kk*2) + selA) ^ swz) << 4);
        const uint32_t qb = ((((uint32_t)(kk*2) + selB) ^ swz) << 4);
        uint32_t a[2][4];
        #pragma unroll
        for (int mt = 0; mt < 2; mt++)
            LDSM_X4(a[mt][0], a[mt][1], a[mt][2], a[mt][3],
                    sA + (rowA + mt*16)*G1_STR + qa);
        uint32_t bf[2][4];
        #pragma unroll
        for (int bp = 0; bp < 2; bp++)
            LDSM_X4(bf[bp][0], bf[bp][1], bf[bp][2], bf[bp][3],
                    sB + (rowB + bp*16)*G1_STR + qb);
        #pragma unroll
        for (int mt = 0; mt < 2; mt++)
            #pragma unroll
            for (int nt = 0; nt < 4; nt++) {
                const int bp = nt >> 1, be = (nt & 1)*2;
                MMA16816F16(acc[mt][nt], a[mt], bf[bp][be], bf[bp][be+1]);
            }
    }

    // ---- epilogue: bias + relu -> fp16 ----
    const float* bias = ct ? br : bl;
    __half* dst = ct ? g_hr : g_hl;
    const int r0 = wj*32 + (lid >> 2);
    const int n0 = wc*32 + (lid & 3)*2;
    #pragma unroll
    for (int mt = 0; mt < 2; mt++) {
        #pragma unroll
        for (int nt = 0; nt < 4; nt++) {
            const int n = n0 + nt*8;
            const float b0v = bias[n], b1v = bias[n+1];
            const size_t rg = (size_t)rt*64 + r0 + mt*16;
            *reinterpret_cast<__half2*>(dst + rg*H_ + n) =
                __floats2half2_rn(fmaxf(acc[mt][nt][0] + b0v, 0.f),
                                  fmaxf(acc[mt][nt][1] + b1v, 0.f));
            *reinterpret_cast<__half2*>(dst + (rg+8)*H_ + n) =
                __floats2half2_rn(fmaxf(acc[mt][nt][2] + b0v, 0.f),
                                  fmaxf(acc[mt][nt][3] + b1v, 0.f));
        }
    }
}

// ---------------------------------------------------------------------------
// GEMM2: t = hl @ Wbc^T; 128 rows x 128 cols (ct selects k half), K=128.
//   B row n (= output g) built on the fly: Wbc[n][h] = Wbil[ct][h][n] (fp32,
//   L2-resident, strided). Single fp16 pass; warp tile 64x32.
//   Output col n_glob = ct*128 + g at g_t[row*256 + n_glob].
// ---------------------------------------------------------------------------
#define SM_G2 (2*128*256)                  // 65536

__global__ void __launch_bounds__(256) gemm2_kernel(const float* __restrict__ Wbil)
{
    extern __shared__ __align__(16) char smem[];
    const uint32_t sA = smem_u32(smem);
    const uint32_t sB = sA + 128*256;

    const int tid = threadIdx.x;
    const int wid = tid >> 5;
    const int lid = tid & 31;
    const int ct  = blockIdx.x;
    const int rt  = blockIdx.y;
    const size_t arow = (size_t)rt * 128;

    // ---- A: hl rows, direct fp16 16B chunks ----
    #pragma unroll
    for (int l = 0; l < 8; l++) {
        int idx = tid + l*256;             // 0..2047
        int r = idx >> 4, q = idx & 15;
        float4 v = *reinterpret_cast<const float4*>(g_hl + (arow + r)*H_ + q*8);
        *reinterpret_cast<float4*>(smem + (r << 8) + ((q ^ (r & 7)) << 4)) = v;
    }
    // ---- B: row n needs Wbil[ct][h][n] over h (stride-128 fp32 gather) ----
    #pragma unroll
    for (int l = 0; l < 8; l++) {
        int idx = tid + l*256;
        int n = idx >> 4, q = idx & 15;
        const float* p = Wbil + (size_t)ct*H_*H_ + (size_t)(q*8)*H_ + n;
        float4 v0, v1;
        v0.x = p[0];      v0.y = p[H_];     v0.z = p[2*H_];   v0.w = p[3*H_];
        v1.x = p[4*H_];   v1.y = p[5*H_];   v1.z = p[6*H_];   v1.w = p[7*H_];
        *reinterpret_cast<uint4*>(smem + 128*256 + (n << 8) + ((q ^ (n & 7)) << 4)) = pack8(v0, v1);
    }
    __syncthreads();

    const int wj = wid >> 2;
    const int wc = wid & 3;
    const uint32_t swz  = (uint32_t)(lid & 7);
    const uint32_t rowA = (uint32_t)(wj*64 + (lid & 15));
    const uint32_t selA = (uint32_t)(lid >> 4);
    const uint32_t rowB = (uint32_t)(wc*32 + (lid & 7) + ((lid >> 4) << 3));
    const uint32_t selB = (uint32_t)((lid >> 3) & 1);

    float acc[4][4][4];
    #pragma unroll
    for (int mt = 0; mt < 4; mt++)
        #pragma unroll
        for (int nt = 0; nt < 4; nt++)
            #pragma unroll
            for (int e = 0; e < 4; e++) acc[mt][nt][e] = 0.0f;

    #pragma unroll
    for (int kk = 0; kk < 8; kk++) {
        const uint32_t qa = ((((uint32_t)(kk*2) + selA) ^ swz) << 4);
        const uint32_t qb = ((((uint32_t)(kk*2) + selB) ^ swz) << 4);
        uint32_t a[4][4];
        #pragma unroll
        for (int mt = 0; mt < 4; mt++)
            LDSM_X4(a[mt][0], a[mt][1], a[mt][2], a[mt][3],
                    sA + ((rowA + mt*16) << 8) + qa);
        uint32_t bf[2][4];
        #pragma unroll
        for (int bp = 0; bp < 2; bp++)
            LDSM_X4(bf[bp][0], bf[bp][1], bf[bp][2], bf[bp][3],
                    sB + ((rowB + bp*16) << 8) + qb);
        #pragma unroll
        for (int mt = 0; mt < 4; mt++)
            #pragma unroll
            for (int nt = 0; nt < 4; nt++) {
                const int bp = nt >> 1, be = (nt & 1)*2;
                MMA16816F16(acc[mt][nt], a[mt], bf[bp][be], bf[bp][be+1]);
            }
    }

    const int r0 = wj*64 + (lid >> 2);
    const int n0 = ct*128 + wc*32 + (lid & 3)*2;
    #pragma unroll
    for (int mt = 0; mt < 4; mt++) {
        #pragma unroll
        for (int nt = 0; nt < 4; nt++) {
            const int n = n0 + nt*8;
            const size_t ra = arow + r0 + mt*16;
            *reinterpret_cast<__half2*>(g_t + ra*256 + n) =
                __floats2half2_rn(acc[mt][nt][0], acc[mt][nt][1]);
            *reinterpret_cast<__half2*>(g_t + (ra+8)*256 + n) =
                __floats2half2_rn(acc[mt][nt][2], acc[mt][nt][3]);
        }
    }
}

// ---------------------------------------------------------------------------
// Pairwise GEMM, fp16 single-pass HMMA (unchanged, verified)
// ---------------------------------------------------------------------------
#define SLAB_   (PJ_*256)
#define SM_PAIR (2*SLAB_)

__global__ void __launch_bounds__(256, 2) pair_kernel(
    const float* __restrict__ bbil, float* __restrict__ out)
{
    extern __shared__ __align__(16) char smem[];
    const uint32_t sA = smem_u32(smem);
    const uint32_t sB = sA + SLAB_;

    const int tid = threadIdx.x;
    const int wid = tid >> 5;
    const int lid = tid & 31;
    const int b   = blockIdx.z;
    const int cb  = blockIdx.x * PC_;
    const int jb  = blockIdx.y * PJ_;

    {
        const __half* Asrc = g_hr + (size_t)(b*N_ + jb)*H_;
        const __half* Bsrc = g_t  + (size_t)b*N_*2*H_ + (size_t)cb*H_;
        #pragma unroll
        for (int l = 0; l < 8; l++) {
            int idx = tid + l*256;
            int r = idx >> 4, q = idx & 15;
            float4 v = *reinterpret_cast<const float4*>(Asrc + r*H_ + q*8);
            *reinterpret_cast<float4*>(smem + (r << 8) + ((q ^ (r & 7)) << 4)) = v;
        }
        #pragma unroll
        for (int l = 0; l < 8; l++) {
            int idx = tid + l*256;
            int r = idx >> 4, q = idx & 15;
            float4 v = *reinterpret_cast<const float4*>(Bsrc + r*H_ + q*8);
            *reinterpret_cast<float4*>(smem + SLAB_ + (r << 8)
                                       + ((q ^ (r & 7)) << 4)) = v;
        }
    }
    __syncthreads();

    const int wj = wid >> 2;
    const int wc = wid & 3;
    const uint32_t swz  = (uint32_t)(lid & 7);
    const uint32_t rowA = (uint32_t)(wj*64 + (lid & 15));
    const uint32_t selA = (uint32_t)(lid >> 4);
    const uint32_t rowB = (uint32_t)(wc*32 + (lid & 7) + ((lid >> 4) << 3));
    const uint32_t selB = (uint32_t)((lid >> 3) & 1);

    float acc[4][4][4];
    #pragma unroll
    for (int mt = 0; mt < 4; mt++)
        #pragma unroll
        for (int nt = 0; nt < 4; nt++)
            #pragma unroll
            for (int e = 0; e < 4; e++) acc[mt][nt][e] = 0.0f;

    #pragma unroll
    for (int kk = 0; kk < 8; kk++) {
        const uint32_t qa = ((((uint32_t)(kk*2) + selA) ^ swz) << 4);
        const uint32_t qb = ((((uint32_t)(kk*2) + selB) ^ swz) << 4);
        uint32_t a[4][4];
        #pragma unroll
        for (int mt = 0; mt < 4; mt++)
            LDSM_X4(a[mt][0], a[mt][1], a[mt][2], a[mt][3],
                    sA + ((rowA + mt*16) << 8) + qa);
        uint32_t bf[2][4];
        #pragma unroll
        for (int bp = 0; bp < 2; bp++)
            LDSM_X4(bf[bp][0], bf[bp][1], bf[bp][2], bf[bp][3],
                    sB + ((rowB + bp*16) << 8) + qb);
        #pragma unroll
        for (int mt = 0; mt < 4; mt++)
            #pragma unroll
            for (int nt = 0; nt < 4; nt++) {
                const int bp = nt >> 1, be = (nt & 1)*2;
                MMA16816F16(acc[mt][nt], a[mt], bf[bp][be], bf[bp][be+1]);
            }
    }

    const float bb0 = bbil[0];
    const float bb1 = bbil[1];
    const int jg = jb + wj*64 + (lid >> 2);
    const int ig = ((cb + wc*32) >> 1) + (lid & 3);
    #pragma unroll
    for (int mt = 0; mt < 4; mt++) {
        const int j0 = jg + mt*16;
        #pragma unroll
        for (int nt = 0; nt < 4; nt++) {
            const int i0 = ig + nt*4;
            float* o = out + ((size_t)(b*N_ + i0)*N_)*2;
            float2 v0, v1;
            v0.x = acc[mt][nt][0] + bb0;  v0.y = acc[mt][nt][1] + bb1;
            v1.x = acc[mt][nt][2] + bb0;  v1.y = acc[mt][nt][3] + bb1;
            *reinterpret_cast<float2*>(o + (size_t)j0*2)       = v0;
            *reinterpret_cast<float2*>(o + (size_t)(j0 + 8)*2) = v1;
        }
    }
}

// ---------------------------------------------------------------------------
extern "C" void kernel_launch(void* const* d_in, const int* in_sizes, int n_in,
                              void* d_out, int out_size)
{
    const float* x    = (const float*)d_in[0];
    const float* Wl   = (const float*)d_in[1];
    const float* bl   = (const float*)d_in[2];
    const float* Wr   = (const float*)d_in[3];
    const float* br   = (const float*)d_in[4];
    const float* Wbil = (const float*)d_in[5];
    const float* bbil = (const float*)d_in[6];
    float* out = (float*)d_out;
    (void)in_sizes; (void)n_in; (void)out_size;

    cudaFuncSetAttribute(gemm1_kernel,
                         cudaFuncAttributeMaxDynamicSharedMemorySize, SM_G1);
    cudaFuncSetAttribute(gemm2_kernel,
                         cudaFuncAttributeMaxDynamicSharedMemorySize, SM_G2);
    cudaFuncSetAttribute(pair_kernel,
                         cudaFuncAttributeMaxDynamicSharedMemorySize, SM_PAIR);

    gemm1_kernel<<<dim3(2, B_*N_/64), 256, SM_G1>>>(x, Wl, bl, Wr, br);
    gemm2_kernel<<<dim3(2, B_*N_/128), 256, SM_G2>>>(Wbil);
    pair_kernel<<<dim3(2*N_/PC_, N_/PJ_, B_), 256, SM_PAIR>>>(bbil, out);
}